// round 5
// baseline (speedup 1.0000x reference)
#include <cuda_runtime.h>
#include <mma.h>

using namespace nvcuda;

#define BDIM 4096
#define SEQ  2048
#define BATCH 2
#define NH   32
#define NKV  8
#define HD   128

// ---------------- scratch (device globals; no allocations allowed) -------------
__device__ float g_qbuf[(size_t)BATCH * SEQ * NH * HD];   // [b*s, 4096]
__device__ float g_kbuf[(size_t)BATCH * SEQ * NKV * HD];  // [b*s, 1024]
__device__ float g_vbuf[(size_t)BATCH * SEQ * NKV * HD];
__device__ float g_qT[(size_t)BATCH * NH * SEQ * HD];     // [b,h,s,d]
__device__ float g_kT[(size_t)BATCH * NKV * SEQ * HD];
__device__ float g_vT[(size_t)BATCH * NKV * SEQ * HD];
__device__ float g_attn[(size_t)BATCH * SEQ * NH * HD];   // [b*s, 4096]

typedef wmma::fragment<wmma::matrix_a, 16, 16, 8, wmma::precision::tf32, wmma::row_major> FragA;
typedef wmma::fragment<wmma::matrix_b, 16, 16, 8, wmma::precision::tf32, wmma::col_major> FragBc;
typedef wmma::fragment<wmma::matrix_b, 16, 16, 8, wmma::precision::tf32, wmma::row_major> FragBr;
typedef wmma::fragment<wmma::accumulator, 16, 16, 8, float> FragC;

// ---------------- GEMM: C[M,N] = A[M,K] * W[N,K]^T  (tf32 wmma) ----------------
#define GBM 128
#define GBN 128
#define GBK 32
#define GLD 40

__global__ __launch_bounds__(256) void gemm_tf32_nt(
    const float* __restrict__ A, const float* __restrict__ W, float* __restrict__ C,
    int M, int N, int K)
{
    __shared__ float As[GBM * GLD];
    __shared__ float Bs[GBN * GLD];

    int bm = blockIdx.y * GBM;
    int bn = blockIdx.x * GBN;
    int tid = threadIdx.x;
    int warp = tid >> 5;
    int wr = warp >> 1;  // 0..3 : 32-row slab
    int wc = warp & 1;   // 0..1 : 64-col slab

    FragC acc[2][4];
    #pragma unroll
    for (int i = 0; i < 2; i++)
        #pragma unroll
        for (int j = 0; j < 4; j++)
            wmma::fill_fragment(acc[i][j], 0.0f);

    for (int k0 = 0; k0 < K; k0 += GBK) {
        #pragma unroll
        for (int v = 0; v < 4; v++) {
            int idx = tid + v * 256;       // 0..1023
            int r = idx >> 3;              // 0..127
            int c = (idx & 7) * 4;         // 0..28
            float4 ta = *(const float4*)(A + (size_t)(bm + r) * K + k0 + c);
            As[r * GLD + c + 0] = wmma::__float_to_tf32(ta.x);
            As[r * GLD + c + 1] = wmma::__float_to_tf32(ta.y);
            As[r * GLD + c + 2] = wmma::__float_to_tf32(ta.z);
            As[r * GLD + c + 3] = wmma::__float_to_tf32(ta.w);
            float4 tb = *(const float4*)(W + (size_t)(bn + r) * K + k0 + c);
            Bs[r * GLD + c + 0] = wmma::__float_to_tf32(tb.x);
            Bs[r * GLD + c + 1] = wmma::__float_to_tf32(tb.y);
            Bs[r * GLD + c + 2] = wmma::__float_to_tf32(tb.z);
            Bs[r * GLD + c + 3] = wmma::__float_to_tf32(tb.w);
        }
        __syncthreads();

        #pragma unroll
        for (int kk = 0; kk < GBK / 8; kk++) {
            FragA af[2];
            FragBc bf[4];
            #pragma unroll
            for (int i = 0; i < 2; i++)
                wmma::load_matrix_sync(af[i], As + (wr * 32 + i * 16) * GLD + kk * 8, GLD);
            #pragma unroll
            for (int j = 0; j < 4; j++)
                wmma::load_matrix_sync(bf[j], Bs + (wc * 64 + j * 16) * GLD + kk * 8, GLD);
            #pragma unroll
            for (int i = 0; i < 2; i++)
                #pragma unroll
                for (int j = 0; j < 4; j++)
                    wmma::mma_sync(acc[i][j], af[i], bf[j], acc[i][j]);
        }
        __syncthreads();
    }

    #pragma unroll
    for (int i = 0; i < 2; i++)
        #pragma unroll
        for (int j = 0; j < 4; j++)
            wmma::store_matrix_sync(
                C + (size_t)(bm + wr * 32 + i * 16) * N + bn + wc * 64 + j * 16,
                acc[i][j], N, wmma::mem_row_major);
}

// ---------------- RoPE + transpose [b,s,h,d] -> [b,h,s,d] ----------------------
__global__ void rope_tr(const float* __restrict__ in, const float* __restrict__ fc,
                        const float* __restrict__ fs, float* __restrict__ outT,
                        int nh, int total)
{
    int idx = blockIdx.x * blockDim.x + threadIdx.x;
    if (idx >= total) return;
    int i = idx & 63;        // pair index 0..63
    int t = idx >> 6;
    int h = t % nh; t /= nh;
    int s = t % SEQ;
    int b = t / SEQ;
    float c = fc[s * 64 + i];
    float sn = fs[s * 64 + i];
    size_t src = (((size_t)(b * SEQ + s)) * nh + h) * HD + 2 * i;
    float x0 = in[src];
    float x1 = in[src + 1];
    size_t dst = (((size_t)(b * nh + h)) * SEQ + s) * HD + 2 * i;
    outT[dst]     = x0 * c - x1 * sn;
    outT[dst + 1] = x0 * sn + x1 * c;
}

__global__ void tr_v(const float* __restrict__ in, float* __restrict__ outT, int total)
{
    int idx = blockIdx.x * blockDim.x + threadIdx.x;
    if (idx >= total) return;
    int d = idx & 127;
    int t = idx >> 7;
    int h = t % NKV; t /= NKV;
    int s = t % SEQ;
    int b = t / SEQ;
    outT[(((size_t)(b * NKV + h)) * SEQ + s) * HD + d] =
        in[(((size_t)(b * SEQ + s)) * NKV + h) * HD + d];
}

// ---------------- Flash attention (causal, GQA), tf32 wmma ---------------------
// block: 256 threads, handles 64 q rows for one (b, h). smem holds Q,K,V,O,S.
#define ALDD 136   // ld for d=128 tiles (pad 8)
#define ALDS 72    // ld for 64-wide score tile
#define ATTN_SMEM_BYTES ((4 * 64 * ALDD + 64 * ALDS + 3 * 64) * 4)

__global__ __launch_bounds__(256) void attn_fa(
    const float* __restrict__ qT, const float* __restrict__ kT,
    const float* __restrict__ vT, float* __restrict__ attn_out)
{
    extern __shared__ float smem_f[];
    float* Qs = smem_f;                 // 64 x ALDD
    float* Ks = Qs + 64 * ALDD;
    float* Vs = Ks + 64 * ALDD;
    float* Os = Vs + 64 * ALDD;
    float* Ss = Os + 64 * ALDD;         // 64 x ALDS
    float* mrow = Ss + 64 * ALDS;
    float* lrow = mrow + 64;
    float* arow = lrow + 64;

    int qt = blockIdx.x;
    int h  = blockIdx.y;
    int b  = blockIdx.z;
    int g  = h >> 2;  // kv head (N_REP = 4)
    int tid = threadIdx.x;
    int warp = tid >> 5;
    int lane = tid & 31;

    const float* Qg = qT + (((size_t)(b * NH + h)) * SEQ + qt * 64) * HD;
    const float* Kg = kT + ((size_t)(b * NKV + g)) * SEQ * HD;
    const float* Vg = vT + ((size_t)(b * NKV + g)) * SEQ * HD;

    const float qscale = 0.088388347648318447f;  // 1/sqrt(128)

    for (int i = tid; i < 64 * 32; i += 256) {
        int r = i >> 5;
        int c = (i & 31) * 4;
        float4 t = *(const float4*)(Qg + (size_t)r * HD + c);
        Qs[r * ALDD + c + 0] = wmma::__float_to_tf32(t.x * qscale);
        Qs[r * ALDD + c + 1] = wmma::__float_to_tf32(t.y * qscale);
        Qs[r * ALDD + c + 2] = wmma::__float_to_tf32(t.z * qscale);
        Qs[r * ALDD + c + 3] = wmma::__float_to_tf32(t.w * qscale);
    }
    for (int i = tid; i < 64 * ALDD; i += 256) Os[i] = 0.0f;
    if (tid < 64) { mrow[tid] = -1e30f; lrow[tid] = 0.0f; }
    __syncthreads();

    for (int kt = 0; kt <= qt; kt++) {
        const float* Kt = Kg + (size_t)kt * 64 * HD;
        const float* Vt = Vg + (size_t)kt * 64 * HD;
        for (int i = tid; i < 64 * 32; i += 256) {
            int r = i >> 5;
            int c = (i & 31) * 4;
            float4 tk = *(const float4*)(Kt + (size_t)r * HD + c);
            Ks[r * ALDD + c + 0] = wmma::__float_to_tf32(tk.x);
            Ks[r * ALDD + c + 1] = wmma::__float_to_tf32(tk.y);
            Ks[r * ALDD + c + 2] = wmma::__float_to_tf32(tk.z);
            Ks[r * ALDD + c + 3] = wmma::__float_to_tf32(tk.w);
            float4 tv = *(const float4*)(Vt + (size_t)r * HD + c);
            Vs[r * ALDD + c + 0] = wmma::__float_to_tf32(tv.x);
            Vs[r * ALDD + c + 1] = wmma::__float_to_tf32(tv.y);
            Vs[r * ALDD + c + 2] = wmma::__float_to_tf32(tv.z);
            Vs[r * ALDD + c + 3] = wmma::__float_to_tf32(tv.w);
        }
        __syncthreads();

        // S = Qs * Ks^T : 4x4 tiles of 16x16, 2 per warp
        #pragma unroll
        for (int tt = 0; tt < 2; tt++) {
            int t = warp * 2 + tt;
            int ti = t >> 2;
            int tj = t & 3;
            FragC sacc;
            wmma::fill_fragment(sacc, 0.0f);
            #pragma unroll
            for (int kk = 0; kk < 16; kk++) {
                FragA af;
                FragBc bf;
                wmma::load_matrix_sync(af, Qs + (ti * 16) * ALDD + kk * 8, ALDD);
                wmma::load_matrix_sync(bf, Ks + (tj * 16) * ALDD + kk * 8, ALDD);
                wmma::mma_sync(sacc, af, bf, sacc);
            }
            wmma::store_matrix_sync(Ss + (ti * 16) * ALDS + tj * 16, sacc, ALDS,
                                    wmma::mem_row_major);
        }
        __syncthreads();

        // online softmax: each warp owns 8 rows
        for (int r0 = 0; r0 < 8; r0++) {
            int row = warp * 8 + r0;
            int qg = qt * 64 + row;
            float v0 = Ss[row * ALDS + lane];
            float v1 = Ss[row * ALDS + lane + 32];
            if (kt * 64 + lane > qg)      v0 = -1e30f;
            if (kt * 64 + lane + 32 > qg) v1 = -1e30f;
            float mx = fmaxf(v0, v1);
            #pragma unroll
            for (int o = 16; o > 0; o >>= 1)
                mx = fmaxf(mx, __shfl_xor_sync(0xffffffffu, mx, o));
            float mo = mrow[row];
            float nm = fmaxf(mo, mx);
            float p0 = __expf(v0 - nm);
            float p1 = __expf(v1 - nm);
            Ss[row * ALDS + lane]      = wmma::__float_to_tf32(p0);
            Ss[row * ALDS + lane + 32] = wmma::__float_to_tf32(p1);
            float sum = p0 + p1;
            #pragma unroll
            for (int o = 16; o > 0; o >>= 1)
                sum += __shfl_xor_sync(0xffffffffu, sum, o);
            if (lane == 0) {
                float al = __expf(mo - nm);
                arow[row] = al;
                mrow[row] = nm;
                lrow[row] = lrow[row] * al + sum;
            }
        }
        __syncthreads();

        // rescale O by alpha
        for (int i = tid; i < 64 * HD; i += 256) {
            int r = i >> 7;
            int c = i & 127;
            Os[r * ALDD + c] *= arow[r];
        }
        __syncthreads();

        // O += P * V : 4x8 tiles of 16x16, 4 per warp
        #pragma unroll
        for (int tt = 0; tt < 4; tt++) {
            int t = warp * 4 + tt;
            int ti = t >> 3;
            int tj = t & 7;
            FragC oacc;
            wmma::load_matrix_sync(oacc, Os + (ti * 16) * ALDD + tj * 16, ALDD,
                                   wmma::mem_row_major);
            #pragma unroll
            for (int kk = 0; kk < 8; kk++) {
                FragA af;
                FragBr bf;
                wmma::load_matrix_sync(af, Ss + (ti * 16) * ALDS + kk * 8, ALDS);
                wmma::load_matrix_sync(bf, Vs + (kk * 8) * ALDD + tj * 16, ALDD);
                wmma::mma_sync(oacc, af, bf, oacc);
            }
            wmma::store_matrix_sync(Os + (ti * 16) * ALDD + tj * 16, oacc, ALDD,
                                    wmma::mem_row_major);
        }
        __syncthreads();
    }

    // normalize and write to [b*s, h*128 + c]
    for (int i = tid; i < 64 * HD; i += 256) {
        int r = i >> 7;
        int c = i & 127;
        float val = Os[r * ALDD + c] / lrow[r];
        attn_out[((size_t)(b * SEQ) + qt * 64 + r) * (NH * HD) + h * HD + c] = val;
    }
}

// ---------------- launch ------------------------------------------------------
extern "C" void kernel_launch(void* const* d_in, const int* in_sizes, int n_in,
                              void* d_out, int out_size)
{
    const float* x  = (const float*)d_in[0];
    const float* wq = (const float*)d_in[1];
    const float* wk = (const float*)d_in[2];
    const float* wv = (const float*)d_in[3];
    const float* wo = (const float*)d_in[4];
    const float* fc = (const float*)d_in[5];
    const float* fs = (const float*)d_in[6];
    // d_in[7] = mask (causal, reproduced in-kernel), d_in[8] = start_pos (0)
    float* out = (float*)d_out;

    float *qbuf, *kbuf, *vbuf, *qT, *kT, *vT, *attn;
    cudaGetSymbolAddress((void**)&qbuf, g_qbuf);
    cudaGetSymbolAddress((void**)&kbuf, g_kbuf);
    cudaGetSymbolAddress((void**)&vbuf, g_vbuf);
    cudaGetSymbolAddress((void**)&qT, g_qT);
    cudaGetSymbolAddress((void**)&kT, g_kT);
    cudaGetSymbolAddress((void**)&vT, g_vT);
    cudaGetSymbolAddress((void**)&attn, g_attn);

    const int M = BATCH * SEQ;  // 4096

    gemm_tf32_nt<<<dim3((NH * HD) / GBN, M / GBM), 256>>>(x, wq, qbuf, M, NH * HD, BDIM);
    gemm_tf32_nt<<<dim3((NKV * HD) / GBN, M / GBM), 256>>>(x, wk, kbuf, M, NKV * HD, BDIM);
    gemm_tf32_nt<<<dim3((NKV * HD) / GBN, M / GBM), 256>>>(x, wv, vbuf, M, NKV * HD, BDIM);

    int nq = M * NH * (HD / 2);
    rope_tr<<<(nq + 255) / 256, 256>>>(qbuf, fc, fs, qT, NH, nq);
    int nk = M * NKV * (HD / 2);
    rope_tr<<<(nk + 255) / 256, 256>>>(kbuf, fc, fs, kT, NKV, nk);
    int nv = M * NKV * HD;
    tr_v<<<(nv + 255) / 256, 256>>>(vbuf, vT, nv);

    cudaFuncSetAttribute(attn_fa, cudaFuncAttributeMaxDynamicSharedMemorySize,
                         ATTN_SMEM_BYTES);
    attn_fa<<<dim3(SEQ / 64, NH, BATCH), 256, ATTN_SMEM_BYTES>>>(qT, kT, vT, attn);

    gemm_tf32_nt<<<dim3(BDIM / GBN, M / GBM), 256>>>(attn, wo, out, M, BDIM, NH * HD);
}

// round 8
// speedup vs baseline: 1.3562x; 1.3562x over previous
#include <cuda_runtime.h>
#include <mma.h>
#include <cstdint>

using namespace nvcuda;

#define BDIM 4096
#define SEQ  2048
#define BATCH 2
#define NH   32
#define NKV  8
#define HD   128

// ---------------- scratch (device globals; no allocations allowed) -------------
__device__ float g_qbuf[(size_t)BATCH * SEQ * NH * HD];   // [b*s, 4096]
__device__ float g_kbuf[(size_t)BATCH * SEQ * NKV * HD];  // [b*s, 1024]
__device__ float g_vbuf[(size_t)BATCH * SEQ * NKV * HD];
__device__ float g_qT[(size_t)BATCH * NH * SEQ * HD];     // [b,h,s,d]
__device__ float g_kT[(size_t)BATCH * NKV * SEQ * HD];
__device__ float g_vT[(size_t)BATCH * NKV * SEQ * HD];
__device__ float g_attn[(size_t)BATCH * SEQ * NH * HD];   // [b*s, 4096]

// ---------------- small helpers ------------------------------------------------
__device__ __forceinline__ uint32_t f2t(float x) {
    uint32_t u;
    asm("cvt.rna.tf32.f32 %0, %1;" : "=r"(u) : "f"(x));
    return u;
}

__device__ __forceinline__ void cp16(float* dst, const float* src) {
    uint32_t d = (uint32_t)__cvta_generic_to_shared(dst);
    asm volatile("cp.async.cg.shared.global [%0], [%1], 16;" :: "r"(d), "l"(src));
}
#define CP_COMMIT() asm volatile("cp.async.commit_group;")
#define CP_WAIT1()  asm volatile("cp.async.wait_group 1;")

// raw tf32 mma m16n8k8 (row.col), fp32 accum, documented layouts:
//  A: a0{r,c} a1{r+8,c} a2{r,c+4} a3{r+8,c+4}   r=lane>>2, c=lane&3
//  B: b0{k,n} b1{k+4,n}                          k=lane&3, n=lane>>2
//  C: c0{r,2c} c1{r,2c+1} c2{r+8,2c} c3{r+8,2c+1}
__device__ __forceinline__ void mma8(float* c, const uint32_t* a, uint32_t b0, uint32_t b1) {
    asm volatile(
        "mma.sync.aligned.m16n8k8.row.col.f32.tf32.tf32.f32 "
        "{%0,%1,%2,%3},{%4,%5,%6,%7},{%8,%9},{%0,%1,%2,%3};"
        : "+f"(c[0]), "+f"(c[1]), "+f"(c[2]), "+f"(c[3])
        : "r"(a[0]), "r"(a[1]), "r"(a[2]), "r"(a[3]), "r"(b0), "r"(b1));
}

typedef wmma::fragment<wmma::matrix_a, 16, 16, 8, wmma::precision::tf32, wmma::row_major> FragA;
typedef wmma::fragment<wmma::matrix_b, 16, 16, 8, wmma::precision::tf32, wmma::col_major> FragBc;
typedef wmma::fragment<wmma::accumulator, 16, 16, 8, float> FragC;

// ---------------- GEMM: C[M,N] = A[M,K] * W[N,K]^T  (tf32, 3-stage cp.async) ---
#define GBM 128
#define GBN 128
#define GBK 32
#define GLD 40
#define GSTG 3
#define GAS (GBM * GLD)                 // floats per A (or B) stage buffer
#define GSTAGE (2 * GAS)                // floats per stage
#define GEMM_SMEM_BYTES (GSTG * GSTAGE * 4)

__device__ __forceinline__ void gemm_load_stage(
    float* st, const float* A, const float* W, int bm, int bn, int K, int k0, int tid)
{
    float* As = st;
    float* Bs = st + GAS;
    #pragma unroll
    for (int v = 0; v < 4; v++) {
        int c = tid + v * 256;          // 0..1023
        int r = c >> 3;
        int c4 = (c & 7) * 4;
        cp16(As + r * GLD + c4, A + (size_t)(bm + r) * K + k0 + c4);
        cp16(Bs + r * GLD + c4, W + (size_t)(bn + r) * K + k0 + c4);
    }
}

__global__ __launch_bounds__(256) void gemm_tf32_nt(
    const float* __restrict__ A, const float* __restrict__ W, float* __restrict__ C,
    int M, int N, int K)
{
    extern __shared__ float smg[];
    int bm = blockIdx.y * GBM;
    int bn = blockIdx.x * GBN;
    int tid = threadIdx.x;
    int warp = tid >> 5;
    int wr = warp >> 1;   // 0..3
    int wc = warp & 1;    // 0..1

    FragC acc[2][4];
    #pragma unroll
    for (int i = 0; i < 2; i++)
        #pragma unroll
        for (int j = 0; j < 4; j++)
            wmma::fill_fragment(acc[i][j], 0.0f);

    int nk = K / GBK;

    #pragma unroll
    for (int s = 0; s < GSTG - 1; s++) {
        if (s < nk) gemm_load_stage(smg + s * GSTAGE, A, W, bm, bn, K, s * GBK, tid);
        CP_COMMIT();
    }

    for (int ks = 0; ks < nk; ks++) {
        CP_WAIT1();
        __syncthreads();
        float* As = smg + (ks % GSTG) * GSTAGE;
        float* Bs = As + GAS;

        #pragma unroll
        for (int kk = 0; kk < GBK / 8; kk++) {
            FragA af[2];
            FragBc bf[4];
            #pragma unroll
            for (int i = 0; i < 2; i++) {
                wmma::load_matrix_sync(af[i], As + (wr * 32 + i * 16) * GLD + kk * 8, GLD);
                #pragma unroll
                for (int e = 0; e < af[i].num_elements; e++)
                    af[i].x[e] = wmma::__float_to_tf32(af[i].x[e]);
            }
            #pragma unroll
            for (int j = 0; j < 4; j++) {
                wmma::load_matrix_sync(bf[j], Bs + (wc * 64 + j * 16) * GLD + kk * 8, GLD);
                #pragma unroll
                for (int e = 0; e < bf[j].num_elements; e++)
                    bf[j].x[e] = wmma::__float_to_tf32(bf[j].x[e]);
            }
            #pragma unroll
            for (int i = 0; i < 2; i++)
                #pragma unroll
                for (int j = 0; j < 4; j++)
                    wmma::mma_sync(acc[i][j], af[i], bf[j], acc[i][j]);
        }
        __syncthreads();

        int kn = ks + GSTG - 1;
        if (kn < nk) gemm_load_stage(smg + (kn % GSTG) * GSTAGE, A, W, bm, bn, K, kn * GBK, tid);
        CP_COMMIT();
    }

    #pragma unroll
    for (int i = 0; i < 2; i++)
        #pragma unroll
        for (int j = 0; j < 4; j++)
            wmma::store_matrix_sync(
                C + (size_t)(bm + wr * 32 + i * 16) * N + bn + wc * 64 + j * 16,
                acc[i][j], N, wmma::mem_row_major);
}

// ---------------- RoPE + transpose [b,s,h,d] -> [b,h,s,d] ----------------------
__global__ void rope_tr(const float* __restrict__ in, const float* __restrict__ fc,
                        const float* __restrict__ fs, float* __restrict__ outT,
                        int nh, int total)
{
    int idx = blockIdx.x * blockDim.x + threadIdx.x;
    if (idx >= total) return;
    int i = idx & 63;
    int t = idx >> 6;
    int h = t % nh; t /= nh;
    int s = t % SEQ;
    int b = t / SEQ;
    float c = fc[s * 64 + i];
    float sn = fs[s * 64 + i];
    size_t src = (((size_t)(b * SEQ + s)) * nh + h) * HD + 2 * i;
    float x0 = in[src];
    float x1 = in[src + 1];
    size_t dst = (((size_t)(b * nh + h)) * SEQ + s) * HD + 2 * i;
    outT[dst]     = x0 * c - x1 * sn;
    outT[dst + 1] = x0 * sn + x1 * c;
}

__global__ void tr_v(const float* __restrict__ in, float* __restrict__ outT, int total)
{
    int idx = blockIdx.x * blockDim.x + threadIdx.x;
    if (idx >= total) return;
    int d = idx & 127;
    int t = idx >> 7;
    int h = t % NKV; t /= NKV;
    int s = t % SEQ;
    int b = t / SEQ;
    outT[(((size_t)(b * NKV + h)) * SEQ + s) * HD + d] =
        in[(((size_t)(b * SEQ + s)) * NKV + h) * HD + d];
}

// ---------------- Flash attention v2 (causal, GQA), raw tf32 mma ---------------
// block = 8 warps = 128 q rows; each warp owns 16 q rows, Q & O in registers.
// KV tiles of 64 keys, 2-stage cp.async double buffer in smem.
#define KLD 132   // pad for K tile: conflict-free S B-frag loads
#define VLD 136   // pad for V tile: conflict-free PV B-frag loads
#define KVSTG_FLOATS (64 * KLD + 64 * VLD)      // 17152 floats per stage
#define ATTN_SMEM_BYTES (2 * KVSTG_FLOATS * 4)  // 137216 B

__device__ __forceinline__ void attn_load_kv(
    float* stage, const float* Kt, const float* Vt, int tid)
{
    float* Ks = stage;
    float* Vs = stage + 64 * KLD;
    #pragma unroll
    for (int v = 0; v < 8; v++) {
        int c = tid + v * 256;          // 0..2047
        int r = c >> 5;
        int c4 = (c & 31) * 4;
        cp16(Ks + r * KLD + c4, Kt + (size_t)r * HD + c4);
        cp16(Vs + r * VLD + c4, Vt + (size_t)r * HD + c4);
    }
}

__global__ __launch_bounds__(256) void attn_fa2(
    const float* __restrict__ qT, const float* __restrict__ kT,
    const float* __restrict__ vT, float* __restrict__ attn_out)
{
    extern __shared__ float sma[];
    int qt = blockIdx.x;
    int h  = blockIdx.y;
    int b  = blockIdx.z;
    int g  = h >> 2;           // N_REP = 4
    int tid = threadIdx.x;
    int warp = tid >> 5;
    int lane = tid & 31;
    int r0 = lane >> 2;        // row-in-tile (quad group)
    int q0 = lane & 3;         // thread-in-quad

    const float* Qg = qT + (((size_t)(b * NH + h)) * SEQ + qt * 128 + warp * 16) * HD;
    const float* Kg = kT + ((size_t)(b * NKV + g)) * SEQ * HD;
    const float* Vg = vT + ((size_t)(b * NKV + g)) * SEQ * HD;
    const float qscale = 0.088388347648318447f;   // 1/sqrt(128)

    // Q fragments: 16 k-tiles over d=128, kept in registers for the whole block
    uint32_t qa[16][4];
    #pragma unroll
    for (int kk = 0; kk < 16; kk++) {
        qa[kk][0] = f2t(Qg[(size_t)r0 * HD + kk * 8 + q0] * qscale);
        qa[kk][1] = f2t(Qg[(size_t)(r0 + 8) * HD + kk * 8 + q0] * qscale);
        qa[kk][2] = f2t(Qg[(size_t)r0 * HD + kk * 8 + q0 + 4] * qscale);
        qa[kk][3] = f2t(Qg[(size_t)(r0 + 8) * HD + kk * 8 + q0 + 4] * qscale);
    }

    float of[16][4];
    #pragma unroll
    for (int dn = 0; dn < 16; dn++) {
        of[dn][0] = 0.0f; of[dn][1] = 0.0f; of[dn][2] = 0.0f; of[dn][3] = 0.0f;
    }
    float m_lo = -1e30f, m_hi = -1e30f, l_lo = 0.0f, l_hi = 0.0f;
    int row_lo = qt * 128 + warp * 16 + r0;
    int row_hi = row_lo + 8;
    int ktmax = 2 * qt + 1;

    attn_load_kv(sma, Kg, Vg, tid);
    CP_COMMIT();

    for (int kt = 0; kt <= ktmax; kt++) {
        if (kt < ktmax)
            attn_load_kv(sma + ((kt + 1) & 1) * KVSTG_FLOATS,
                         Kg + (size_t)(kt + 1) * 64 * HD,
                         Vg + (size_t)(kt + 1) * 64 * HD, tid);
        CP_COMMIT();
        CP_WAIT1();
        __syncthreads();

        bool active = (kt * 64) <= (qt * 128 + warp * 16 + 15);  // warp-uniform
        if (active) {
            const float* Ks = sma + (kt & 1) * KVSTG_FLOATS;
            const float* Vs = Ks + 64 * KLD;

            // ---- S = Q K^T (16 x 64 per warp) ----
            float sf[8][4];
            #pragma unroll
            for (int nn = 0; nn < 8; nn++) {
                sf[nn][0] = 0.0f; sf[nn][1] = 0.0f; sf[nn][2] = 0.0f; sf[nn][3] = 0.0f;
            }
            #pragma unroll
            for (int nn = 0; nn < 8; nn++) {
                const float* Kb = Ks + (nn * 8 + r0) * KLD;
                #pragma unroll
                for (int kk = 0; kk < 16; kk++) {
                    uint32_t b0 = f2t(Kb[kk * 8 + q0]);
                    uint32_t b1 = f2t(Kb[kk * 8 + q0 + 4]);
                    mma8(sf[nn], qa[kk], b0, b1);
                }
            }

            // ---- causal mask (diagonal tiles only) ----
            if (kt >= 2 * qt) {
                #pragma unroll
                for (int nn = 0; nn < 8; nn++) {
                    int c0 = kt * 64 + nn * 8 + 2 * q0;
                    if (c0     > row_lo) sf[nn][0] = -1e30f;
                    if (c0 + 1 > row_lo) sf[nn][1] = -1e30f;
                    if (c0     > row_hi) sf[nn][2] = -1e30f;
                    if (c0 + 1 > row_hi) sf[nn][3] = -1e30f;
                }
            }

            // ---- online softmax in registers ----
            float mx_lo = -1e30f, mx_hi = -1e30f;
            #pragma unroll
            for (int nn = 0; nn < 8; nn++) {
                mx_lo = fmaxf(mx_lo, fmaxf(sf[nn][0], sf[nn][1]));
                mx_hi = fmaxf(mx_hi, fmaxf(sf[nn][2], sf[nn][3]));
            }
            mx_lo = fmaxf(mx_lo, __shfl_xor_sync(0xffffffffu, mx_lo, 1));
            mx_lo = fmaxf(mx_lo, __shfl_xor_sync(0xffffffffu, mx_lo, 2));
            mx_hi = fmaxf(mx_hi, __shfl_xor_sync(0xffffffffu, mx_hi, 1));
            mx_hi = fmaxf(mx_hi, __shfl_xor_sync(0xffffffffu, mx_hi, 2));

            float nm_lo = fmaxf(m_lo, mx_lo);
            float nm_hi = fmaxf(m_hi, mx_hi);
            float al_lo = __expf(m_lo - nm_lo);
            float al_hi = __expf(m_hi - nm_hi);
            m_lo = nm_lo; m_hi = nm_hi;

            float s_lo = 0.0f, s_hi = 0.0f;
            #pragma unroll
            for (int nn = 0; nn < 8; nn++) {
                sf[nn][0] = __expf(sf[nn][0] - m_lo); s_lo += sf[nn][0];
                sf[nn][1] = __expf(sf[nn][1] - m_lo); s_lo += sf[nn][1];
                sf[nn][2] = __expf(sf[nn][2] - m_hi); s_hi += sf[nn][2];
                sf[nn][3] = __expf(sf[nn][3] - m_hi); s_hi += sf[nn][3];
            }
            s_lo += __shfl_xor_sync(0xffffffffu, s_lo, 1);
            s_lo += __shfl_xor_sync(0xffffffffu, s_lo, 2);
            s_hi += __shfl_xor_sync(0xffffffffu, s_hi, 1);
            s_hi += __shfl_xor_sync(0xffffffffu, s_hi, 2);
            l_lo = l_lo * al_lo + s_lo;
            l_hi = l_hi * al_hi + s_hi;

            // ---- rescale O in registers ----
            #pragma unroll
            for (int dn = 0; dn < 16; dn++) {
                of[dn][0] *= al_lo; of[dn][1] *= al_lo;
                of[dn][2] *= al_hi; of[dn][3] *= al_hi;
            }

            // ---- O += P V  (P acc-layout -> A-layout via quad shuffles) ----
            int base = lane & ~3;
            int srcA = base | (q0 >> 1);
            int srcB = base | ((q0 >> 1) + 2);
            #pragma unroll
            for (int kk = 0; kk < 8; kk++) {
                float v0 = __shfl_sync(0xffffffffu, sf[kk][0], srcA);
                float v1 = __shfl_sync(0xffffffffu, sf[kk][1], srcA);
                float v2 = __shfl_sync(0xffffffffu, sf[kk][2], srcA);
                float v3 = __shfl_sync(0xffffffffu, sf[kk][3], srcA);
                float w0 = __shfl_sync(0xffffffffu, sf[kk][0], srcB);
                float w1 = __shfl_sync(0xffffffffu, sf[kk][1], srcB);
                float w2 = __shfl_sync(0xffffffffu, sf[kk][2], srcB);
                float w3 = __shfl_sync(0xffffffffu, sf[kk][3], srcB);
                uint32_t pa[4];
                pa[0] = f2t((q0 & 1) ? v1 : v0);   // row lo, col q0
                pa[1] = f2t((q0 & 1) ? v3 : v2);   // row hi, col q0
                pa[2] = f2t((q0 & 1) ? w1 : w0);   // row lo, col q0+4
                pa[3] = f2t((q0 & 1) ? w3 : w2);   // row hi, col q0+4
                const float* Vb0 = Vs + (kk * 8 + q0) * VLD + r0;
                const float* Vb1 = Vs + (kk * 8 + q0 + 4) * VLD + r0;
                #pragma unroll
                for (int dn = 0; dn < 16; dn++) {
                    uint32_t b0 = f2t(Vb0[dn * 8]);
                    uint32_t b1 = f2t(Vb1[dn * 8]);
                    mma8(of[dn], pa, b0, b1);
                }
            }
        }
        __syncthreads();
    }

    // ---- normalize + write [b*s, h*128 + d] ----
    float inv_lo = 1.0f / l_lo;
    float inv_hi = 1.0f / l_hi;
    float* Olo = attn_out + (size_t)(b * SEQ + row_lo) * (NH * HD) + h * HD;
    float* Ohi = attn_out + (size_t)(b * SEQ + row_hi) * (NH * HD) + h * HD;
    #pragma unroll
    for (int dn = 0; dn < 16; dn++) {
        int c = dn * 8 + 2 * q0;
        *(float2*)(Olo + c) = make_float2(of[dn][0] * inv_lo, of[dn][1] * inv_lo);
        *(float2*)(Ohi + c) = make_float2(of[dn][2] * inv_hi, of[dn][3] * inv_hi);
    }
}

// ---------------- launch ------------------------------------------------------
extern "C" void kernel_launch(void* const* d_in, const int* in_sizes, int n_in,
                              void* d_out, int out_size)
{
    const float* x  = (const float*)d_in[0];
    const float* wq = (const float*)d_in[1];
    const float* wk = (const float*)d_in[2];
    const float* wv = (const float*)d_in[3];
    const float* wo = (const float*)d_in[4];
    const float* fc = (const float*)d_in[5];
    const float* fs = (const float*)d_in[6];
    float* out = (float*)d_out;

    float *qbuf, *kbuf, *vbuf, *qT, *kT, *vT, *attn;
    cudaGetSymbolAddress((void**)&qbuf, g_qbuf);
    cudaGetSymbolAddress((void**)&kbuf, g_kbuf);
    cudaGetSymbolAddress((void**)&vbuf, g_vbuf);
    cudaGetSymbolAddress((void**)&qT, g_qT);
    cudaGetSymbolAddress((void**)&kT, g_kT);
    cudaGetSymbolAddress((void**)&vT, g_vT);
    cudaGetSymbolAddress((void**)&attn, g_attn);

    const int M = BATCH * SEQ;  // 4096

    cudaFuncSetAttribute(gemm_tf32_nt, cudaFuncAttributeMaxDynamicSharedMemorySize,
                         GEMM_SMEM_BYTES);
    cudaFuncSetAttribute(attn_fa2, cudaFuncAttributeMaxDynamicSharedMemorySize,
                         ATTN_SMEM_BYTES);

    gemm_tf32_nt<<<dim3((NH * HD) / GBN, M / GBM), 256, GEMM_SMEM_BYTES>>>(
        x, wq, qbuf, M, NH * HD, BDIM);
    gemm_tf32_nt<<<dim3((NKV * HD) / GBN, M / GBM), 256, GEMM_SMEM_BYTES>>>(
        x, wk, kbuf, M, NKV * HD, BDIM);
    gemm_tf32_nt<<<dim3((NKV * HD) / GBN, M / GBM), 256, GEMM_SMEM_BYTES>>>(
        x, wv, vbuf, M, NKV * HD, BDIM);

    int nq = M * NH * (HD / 2);
    rope_tr<<<(nq + 255) / 256, 256>>>(qbuf, fc, fs, qT, NH, nq);
    int nk = M * NKV * (HD / 2);
    rope_tr<<<(nk + 255) / 256, 256>>>(kbuf, fc, fs, kT, NKV, nk);
    int nv = M * NKV * HD;
    tr_v<<<(nv + 255) / 256, 256>>>(vbuf, vT, nv);

    attn_fa2<<<dim3(SEQ / 128, NH, BATCH), 256, ATTN_SMEM_BYTES>>>(qT, kT, vT, attn);

    gemm_tf32_nt<<<dim3(BDIM / GBN, M / GBM), 256, GEMM_SMEM_BYTES>>>(
        attn, wo, out, M, BDIM, NH * HD);
}

// round 13
// speedup vs baseline: 1.4463x; 1.0664x over previous
#include <cuda_runtime.h>
#include <mma.h>
#include <cstdint>

using namespace nvcuda;

#define BDIM 4096
#define SEQ  2048
#define BATCH 2
#define NH   32
#define NKV  8
#define HD   128

// ---------------- scratch (device globals; no allocations allowed) -------------
__device__ float g_qbuf[(size_t)BATCH * SEQ * NH * HD];   // [b*s, 4096]
__device__ float g_kbuf[(size_t)BATCH * SEQ * NKV * HD];  // [b*s, 1024]
__device__ float g_vbuf[(size_t)BATCH * SEQ * NKV * HD];
__device__ float g_qT[(size_t)BATCH * NH * SEQ * HD];     // [b,h,s,d] tf32-rounded
__device__ float g_kT[(size_t)BATCH * NKV * SEQ * HD];    // tf32-rounded
__device__ float g_vT[(size_t)BATCH * NKV * SEQ * HD];    // tf32-rounded
__device__ float g_attn[(size_t)BATCH * SEQ * NH * HD];   // [b*s, 4096]
__device__ float g_xr[(size_t)BATCH * SEQ * BDIM];        // tf32-rounded x
__device__ float g_wr[(size_t)BDIM * BDIM];               // tf32-rounded weight

// ---------------- small helpers ------------------------------------------------
__device__ __forceinline__ uint32_t f2t(float x) {
    uint32_t u;
    asm("cvt.rna.tf32.f32 %0, %1;" : "=r"(u) : "f"(x));
    return u;
}

__device__ __forceinline__ void cp16(void* dst, const void* src) {
    uint32_t d = (uint32_t)__cvta_generic_to_shared(dst);
    asm volatile("cp.async.cg.shared.global [%0], [%1], 16;" :: "r"(d), "l"(src));
}
#define CP_COMMIT() asm volatile("cp.async.commit_group;")
#define CP_WAIT1()  asm volatile("cp.async.wait_group 1;")

typedef wmma::fragment<wmma::matrix_a, 16, 16, 8, wmma::precision::tf32, wmma::row_major> FragA;
typedef wmma::fragment<wmma::matrix_b, 16, 16, 8, wmma::precision::tf32, wmma::col_major> FragBc;
typedef wmma::fragment<wmma::accumulator, 16, 16, 8, float> FragC;

// ---------------- GEMM: C[M,N] = A[M,K] * W[N,K]^T  (tf32, pre-rounded) --------
// CTA 128x256, 8 warps (2x4), warp tile 64x64 (4x4 wmma 16x16x8).
// Inputs MUST be tf32-pre-rounded -> no cvt in inner loop (HW truncation exact).
#define GBM 128
#define GBN 256
#define GBK 32
#define GLD 36                          // conflict-free: 36 mod 32 strides distinct
#define GAS (GBM * GLD)                 // 4608 floats
#define GBS (GBN * GLD)                 // 9216 floats
#define GSTAGE (GAS + GBS)              // 13824 floats per stage
#define GSTG 3
#define GEMM_SMEM_BYTES (GSTG * GSTAGE * 4)   // 165888 B

__device__ __forceinline__ void gemm_load_stage(
    float* st, const float* A, const float* W, int bm, int bn, int K, int k0, int tid)
{
    float* As = st;
    float* Bs = st + GAS;
    #pragma unroll
    for (int v = 0; v < 4; v++) {
        int idx = tid + v * 256;        // 0..1023
        int r = idx >> 3;
        int seg = (idx & 7) * 4;
        cp16(As + r * GLD + seg, A + (size_t)(bm + r) * K + k0 + seg);
    }
    #pragma unroll
    for (int v = 0; v < 8; v++) {
        int idx = tid + v * 256;        // 0..2047
        int r = idx >> 3;
        int seg = (idx & 7) * 4;
        cp16(Bs + r * GLD + seg, W + (size_t)(bn + r) * K + k0 + seg);
    }
}

__global__ __launch_bounds__(256, 1) void gemm_tf32_nt(
    const float* __restrict__ A, const float* __restrict__ W, float* __restrict__ C,
    int M, int N, int K)
{
    extern __shared__ float smg[];
    int bm = blockIdx.y * GBM;
    int bn = blockIdx.x * GBN;
    int tid = threadIdx.x;
    int warp = tid >> 5;
    int wr = warp >> 2;   // 0..1 : 64-row slab
    int wc = warp & 3;    // 0..3 : 64-col slab

    FragC acc[4][4];
    #pragma unroll
    for (int i = 0; i < 4; i++)
        #pragma unroll
        for (int j = 0; j < 4; j++)
            wmma::fill_fragment(acc[i][j], 0.0f);

    int nk = K / GBK;

    #pragma unroll
    for (int s = 0; s < GSTG - 1; s++) {
        if (s < nk) gemm_load_stage(smg + s * GSTAGE, A, W, bm, bn, K, s * GBK, tid);
        CP_COMMIT();
    }

    for (int ks = 0; ks < nk; ks++) {
        CP_WAIT1();
        __syncthreads();
        float* As = smg + (ks % GSTG) * GSTAGE;
        float* Bs = As + GAS;

        #pragma unroll
        for (int kk = 0; kk < GBK / 8; kk++) {
            FragA af[4];
            FragBc bf[4];
            #pragma unroll
            for (int i = 0; i < 4; i++)
                wmma::load_matrix_sync(af[i], As + (wr * 64 + i * 16) * GLD + kk * 8, GLD);
            #pragma unroll
            for (int j = 0; j < 4; j++)
                wmma::load_matrix_sync(bf[j], Bs + (wc * 64 + j * 16) * GLD + kk * 8, GLD);
            #pragma unroll
            for (int i = 0; i < 4; i++)
                #pragma unroll
                for (int j = 0; j < 4; j++)
                    wmma::mma_sync(acc[i][j], af[i], bf[j], acc[i][j]);
        }
        __syncthreads();

        int kn = ks + GSTG - 1;
        if (kn < nk) gemm_load_stage(smg + (kn % GSTG) * GSTAGE, A, W, bm, bn, K, kn * GBK, tid);
        CP_COMMIT();
    }

    #pragma unroll
    for (int i = 0; i < 4; i++)
        #pragma unroll
        for (int j = 0; j < 4; j++)
            wmma::store_matrix_sync(
                C + (size_t)(bm + wr * 64 + i * 16) * N + bn + wc * 64 + j * 16,
                acc[i][j], N, wmma::mem_row_major);
}

// ---------------- tf32 RNA pre-rounding ----------------------------------------
__global__ void round_tf32(const float* __restrict__ in, float* __restrict__ out, int n)
{
    int i = (blockIdx.x * blockDim.x + threadIdx.x) * 4;
    if (i >= n) return;
    float4 v = *(const float4*)(in + i);
    v.x = __uint_as_float(f2t(v.x));
    v.y = __uint_as_float(f2t(v.y));
    v.z = __uint_as_float(f2t(v.z));
    v.w = __uint_as_float(f2t(v.w));
    *(float4*)(out + i) = v;
}

// ---------------- RoPE + transpose [b,s,h,d] -> [b,h,s,d], tf32-rounded out ----
__global__ void rope_tr(const float* __restrict__ in, const float* __restrict__ fc,
                        const float* __restrict__ fs, float* __restrict__ outT,
                        int nh, int total)
{
    int idx = blockIdx.x * blockDim.x + threadIdx.x;
    if (idx >= total) return;
    int i = idx & 63;
    int t = idx >> 6;
    int h = t % nh; t /= nh;
    int s = t % SEQ;
    int b = t / SEQ;
    float c = fc[s * 64 + i];
    float sn = fs[s * 64 + i];
    size_t src = (((size_t)(b * SEQ + s)) * nh + h) * HD + 2 * i;
    float x0 = in[src];
    float x1 = in[src + 1];
    size_t dst = (((size_t)(b * nh + h)) * SEQ + s) * HD + 2 * i;
    outT[dst]     = __uint_as_float(f2t(x0 * c - x1 * sn));
    outT[dst + 1] = __uint_as_float(f2t(x0 * sn + x1 * c));
}

__global__ void tr_v(const float* __restrict__ in, float* __restrict__ outT, int total)
{
    int idx = blockIdx.x * blockDim.x + threadIdx.x;
    if (idx >= total) return;
    int d = idx & 127;
    int t = idx >> 7;
    int h = t % NKV; t /= NKV;
    int s = t % SEQ;
    int b = t / SEQ;
    outT[(((size_t)(b * NKV + h)) * SEQ + s) * HD + d] =
        __uint_as_float(f2t(in[(((size_t)(b * SEQ + s)) * NKV + h) * HD + d]));
}

// ---------------- Flash attention v2 (causal, GQA), raw tf32 mma ---------------
// K/V/Q arrive tf32-pre-rounded -> no cvt on K/V operand loads.
__device__ __forceinline__ void mma8(float* c, const uint32_t* a, uint32_t b0, uint32_t b1) {
    asm volatile(
        "mma.sync.aligned.m16n8k8.row.col.f32.tf32.tf32.f32 "
        "{%0,%1,%2,%3},{%4,%5,%6,%7},{%8,%9},{%0,%1,%2,%3};"
        : "+f"(c[0]), "+f"(c[1]), "+f"(c[2]), "+f"(c[3])
        : "r"(a[0]), "r"(a[1]), "r"(a[2]), "r"(a[3]), "r"(b0), "r"(b1));
}

#define KLD 132
#define VLD 136
#define KVSTG_FLOATS (64 * KLD + 64 * VLD)
#define ATTN_SMEM_BYTES (2 * KVSTG_FLOATS * 4)

__device__ __forceinline__ void attn_load_kv(
    float* stage, const float* Kt, const float* Vt, int tid)
{
    float* Ks = stage;
    float* Vs = stage + 64 * KLD;
    #pragma unroll
    for (int v = 0; v < 8; v++) {
        int c = tid + v * 256;
        int r = c >> 5;
        int c4 = (c & 31) * 4;
        cp16(Ks + r * KLD + c4, Kt + (size_t)r * HD + c4);
        cp16(Vs + r * VLD + c4, Vt + (size_t)r * HD + c4);
    }
}

__global__ __launch_bounds__(256) void attn_fa2(
    const float* __restrict__ qT, const float* __restrict__ kT,
    const float* __restrict__ vT, float* __restrict__ attn_out)
{
    extern __shared__ float sma[];
    int qt = blockIdx.x;
    int h  = blockIdx.y;
    int b  = blockIdx.z;
    int g  = h >> 2;
    int tid = threadIdx.x;
    int warp = tid >> 5;
    int lane = tid & 31;
    int r0 = lane >> 2;
    int q0 = lane & 3;

    const float* Qg = qT + (((size_t)(b * NH + h)) * SEQ + qt * 128 + warp * 16) * HD;
    const float* Kg = kT + ((size_t)(b * NKV + g)) * SEQ * HD;
    const float* Vg = vT + ((size_t)(b * NKV + g)) * SEQ * HD;
    const float qscale = 0.088388347648318447f;

    uint32_t qa[16][4];
    #pragma unroll
    for (int kk = 0; kk < 16; kk++) {
        qa[kk][0] = f2t(Qg[(size_t)r0 * HD + kk * 8 + q0] * qscale);
        qa[kk][1] = f2t(Qg[(size_t)(r0 + 8) * HD + kk * 8 + q0] * qscale);
        qa[kk][2] = f2t(Qg[(size_t)r0 * HD + kk * 8 + q0 + 4] * qscale);
        qa[kk][3] = f2t(Qg[(size_t)(r0 + 8) * HD + kk * 8 + q0 + 4] * qscale);
    }

    float of[16][4];
    #pragma unroll
    for (int dn = 0; dn < 16; dn++) {
        of[dn][0] = 0.0f; of[dn][1] = 0.0f; of[dn][2] = 0.0f; of[dn][3] = 0.0f;
    }
    float m_lo = -1e30f, m_hi = -1e30f, l_lo = 0.0f, l_hi = 0.0f;
    int row_lo = qt * 128 + warp * 16 + r0;
    int row_hi = row_lo + 8;
    int ktmax = 2 * qt + 1;

    attn_load_kv(sma, Kg, Vg, tid);
    CP_COMMIT();

    for (int kt = 0; kt <= ktmax; kt++) {
        if (kt < ktmax)
            attn_load_kv(sma + ((kt + 1) & 1) * KVSTG_FLOATS,
                         Kg + (size_t)(kt + 1) * 64 * HD,
                         Vg + (size_t)(kt + 1) * 64 * HD, tid);
        CP_COMMIT();
        CP_WAIT1();
        __syncthreads();

        bool active = (kt * 64) <= (qt * 128 + warp * 16 + 15);
        if (active) {
            const float* Ks = sma + (kt & 1) * KVSTG_FLOATS;
            const float* Vs = Ks + 64 * KLD;

            float sf[8][4];
            #pragma unroll
            for (int nn = 0; nn < 8; nn++) {
                sf[nn][0] = 0.0f; sf[nn][1] = 0.0f; sf[nn][2] = 0.0f; sf[nn][3] = 0.0f;
            }
            #pragma unroll
            for (int nn = 0; nn < 8; nn++) {
                const uint32_t* Kb = (const uint32_t*)(Ks + (nn * 8 + r0) * KLD);
                #pragma unroll
                for (int kk = 0; kk < 16; kk++) {
                    uint32_t b0 = Kb[kk * 8 + q0];        // pre-rounded tf32 bits
                    uint32_t b1 = Kb[kk * 8 + q0 + 4];
                    mma8(sf[nn], qa[kk], b0, b1);
                }
            }

            if (kt >= 2 * qt) {
                #pragma unroll
                for (int nn = 0; nn < 8; nn++) {
                    int c0 = kt * 64 + nn * 8 + 2 * q0;
                    if (c0     > row_lo) sf[nn][0] = -1e30f;
                    if (c0 + 1 > row_lo) sf[nn][1] = -1e30f;
                    if (c0     > row_hi) sf[nn][2] = -1e30f;
                    if (c0 + 1 > row_hi) sf[nn][3] = -1e30f;
                }
            }

            float mx_lo = -1e30f, mx_hi = -1e30f;
            #pragma unroll
            for (int nn = 0; nn < 8; nn++) {
                mx_lo = fmaxf(mx_lo, fmaxf(sf[nn][0], sf[nn][1]));
                mx_hi = fmaxf(mx_hi, fmaxf(sf[nn][2], sf[nn][3]));
            }
            mx_lo = fmaxf(mx_lo, __shfl_xor_sync(0xffffffffu, mx_lo, 1));
            mx_lo = fmaxf(mx_lo, __shfl_xor_sync(0xffffffffu, mx_lo, 2));
            mx_hi = fmaxf(mx_hi, __shfl_xor_sync(0xffffffffu, mx_hi, 1));
            mx_hi = fmaxf(mx_hi, __shfl_xor_sync(0xffffffffu, mx_hi, 2));

            float nm_lo = fmaxf(m_lo, mx_lo);
            float nm_hi = fmaxf(m_hi, mx_hi);
            float al_lo = __expf(m_lo - nm_lo);
            float al_hi = __expf(m_hi - nm_hi);
            m_lo = nm_lo; m_hi = nm_hi;

            float s_lo = 0.0f, s_hi = 0.0f;
            #pragma unroll
            for (int nn = 0; nn < 8; nn++) {
                sf[nn][0] = __expf(sf[nn][0] - m_lo); s_lo += sf[nn][0];
                sf[nn][1] = __expf(sf[nn][1] - m_lo); s_lo += sf[nn][1];
                sf[nn][2] = __expf(sf[nn][2] - m_hi); s_hi += sf[nn][2];
                sf[nn][3] = __expf(sf[nn][3] - m_hi); s_hi += sf[nn][3];
            }
            s_lo += __shfl_xor_sync(0xffffffffu, s_lo, 1);
            s_lo += __shfl_xor_sync(0xffffffffu, s_lo, 2);
            s_hi += __shfl_xor_sync(0xffffffffu, s_hi, 1);
            s_hi += __shfl_xor_sync(0xffffffffu, s_hi, 2);
            l_lo = l_lo * al_lo + s_lo;
            l_hi = l_hi * al_hi + s_hi;

            #pragma unroll
            for (int dn = 0; dn < 16; dn++) {
                of[dn][0] *= al_lo; of[dn][1] *= al_lo;
                of[dn][2] *= al_hi; of[dn][3] *= al_hi;
            }

            int base = lane & ~3;
            int srcA = base | (q0 >> 1);
            int srcB = base | ((q0 >> 1) + 2);
            #pragma unroll
            for (int kk = 0; kk < 8; kk++) {
                float v0 = __shfl_sync(0xffffffffu, sf[kk][0], srcA);
                float v1 = __shfl_sync(0xffffffffu, sf[kk][1], srcA);
                float v2 = __shfl_sync(0xffffffffu, sf[kk][2], srcA);
                float v3 = __shfl_sync(0xffffffffu, sf[kk][3], srcA);
                float w0 = __shfl_sync(0xffffffffu, sf[kk][0], srcB);
                float w1 = __shfl_sync(0xffffffffu, sf[kk][1], srcB);
                float w2 = __shfl_sync(0xffffffffu, sf[kk][2], srcB);
                float w3 = __shfl_sync(0xffffffffu, sf[kk][3], srcB);
                uint32_t pa[4];
                pa[0] = f2t((q0 & 1) ? v1 : v0);
                pa[1] = f2t((q0 & 1) ? v3 : v2);
                pa[2] = f2t((q0 & 1) ? w1 : w0);
                pa[3] = f2t((q0 & 1) ? w3 : w2);
                const uint32_t* Vb0 = (const uint32_t*)(Vs + (kk * 8 + q0) * VLD) + r0;
                const uint32_t* Vb1 = (const uint32_t*)(Vs + (kk * 8 + q0 + 4) * VLD) + r0;
                #pragma unroll
                for (int dn = 0; dn < 16; dn++) {
                    uint32_t b0 = Vb0[dn * 8];            // pre-rounded tf32 bits
                    uint32_t b1 = Vb1[dn * 8];
                    mma8(of[dn], pa, b0, b1);
                }
            }
        }
        __syncthreads();
    }

    float inv_lo = 1.0f / l_lo;
    float inv_hi = 1.0f / l_hi;
    float* Olo = attn_out + (size_t)(b * SEQ + row_lo) * (NH * HD) + h * HD;
    float* Ohi = attn_out + (size_t)(b * SEQ + row_hi) * (NH * HD) + h * HD;
    #pragma unroll
    for (int dn = 0; dn < 16; dn++) {
        int c = dn * 8 + 2 * q0;
        *(float2*)(Olo + c) = make_float2(of[dn][0] * inv_lo, of[dn][1] * inv_lo);
        *(float2*)(Ohi + c) = make_float2(of[dn][2] * inv_hi, of[dn][3] * inv_hi);
    }
}

// ---------------- launch ------------------------------------------------------
extern "C" void kernel_launch(void* const* d_in, const int* in_sizes, int n_in,
                              void* d_out, int out_size)
{
    const float* x  = (const float*)d_in[0];
    const float* wq = (const float*)d_in[1];
    const float* wk = (const float*)d_in[2];
    const float* wv = (const float*)d_in[3];
    const float* wo = (const float*)d_in[4];
    const float* fc = (const float*)d_in[5];
    const float* fs = (const float*)d_in[6];
    float* out = (float*)d_out;

    float *qbuf, *kbuf, *vbuf, *qT, *kT, *vT, *attn, *xr, *wr;
    cudaGetSymbolAddress((void**)&qbuf, g_qbuf);
    cudaGetSymbolAddress((void**)&kbuf, g_kbuf);
    cudaGetSymbolAddress((void**)&vbuf, g_vbuf);
    cudaGetSymbolAddress((void**)&qT, g_qT);
    cudaGetSymbolAddress((void**)&kT, g_kT);
    cudaGetSymbolAddress((void**)&vT, g_vT);
    cudaGetSymbolAddress((void**)&attn, g_attn);
    cudaGetSymbolAddress((void**)&xr, g_xr);
    cudaGetSymbolAddress((void**)&wr, g_wr);

    const int M = BATCH * SEQ;  // 4096

    cudaFuncSetAttribute(gemm_tf32_nt, cudaFuncAttributeMaxDynamicSharedMemorySize,
                         GEMM_SMEM_BYTES);
    cudaFuncSetAttribute(attn_fa2, cudaFuncAttributeMaxDynamicSharedMemorySize,
                         ATTN_SMEM_BYTES);

    const int RB = 256;
    int nx = M * BDIM;
    round_tf32<<<nx / 4 / RB, RB>>>(x, xr, nx);

    int nwq = BDIM * BDIM;
    round_tf32<<<nwq / 4 / RB, RB>>>(wq, wr, nwq);
    gemm_tf32_nt<<<dim3((NH * HD) / GBN, M / GBM), 256, GEMM_SMEM_BYTES>>>(
        xr, wr, qbuf, M, NH * HD, BDIM);

    int nwk = NKV * HD * BDIM;
    round_tf32<<<nwk / 4 / RB, RB>>>(wk, wr, nwk);
    gemm_tf32_nt<<<dim3((NKV * HD) / GBN, M / GBM), 256, GEMM_SMEM_BYTES>>>(
        xr, wr, kbuf, M, NKV * HD, BDIM);

    round_tf32<<<nwk / 4 / RB, RB>>>(wv, wr, nwk);
    gemm_tf32_nt<<<dim3((NKV * HD) / GBN, M / GBM), 256, GEMM_SMEM_BYTES>>>(
        xr, wr, vbuf, M, NKV * HD, BDIM);

    int nq = M * NH * (HD / 2);
    rope_tr<<<(nq + 255) / 256, 256>>>(qbuf, fc, fs, qT, NH, nq);
    int nk = M * NKV * (HD / 2);
    rope_tr<<<(nk + 255) / 256, 256>>>(kbuf, fc, fs, kT, NKV, nk);
    int nv = M * NKV * HD;
    tr_v<<<(nv + 255) / 256, 256>>>(vbuf, vT, nv);

    attn_fa2<<<dim3(SEQ / 128, NH, BATCH), 256, ATTN_SMEM_BYTES>>>(qT, kT, vT, attn);

    // round attn in place, wo into wr, then output GEMM
    round_tf32<<<nx / 4 / RB, RB>>>(attn, attn, nx);
    round_tf32<<<nwq / 4 / RB, RB>>>(wo, wr, nwq);
    gemm_tf32_nt<<<dim3(BDIM / GBN, M / GBM), 256, GEMM_SMEM_BYTES>>>(
        attn, wr, out, M, BDIM, NH * HD);
}

// round 15
// speedup vs baseline: 1.4524x; 1.0042x over previous
#include <cuda_runtime.h>
#include <mma.h>
#include <cstdint>

using namespace nvcuda;

#define BDIM 4096
#define SEQ  2048
#define BATCH 2
#define NH   32
#define NKV  8
#define HD   128

// ---------------- scratch (device globals; no allocations allowed) -------------
__device__ float g_qbuf[(size_t)BATCH * SEQ * NH * HD];   // [b*s, 4096]
__device__ float g_kbuf[(size_t)BATCH * SEQ * NKV * HD];  // [b*s, 1024]
__device__ float g_vbuf[(size_t)BATCH * SEQ * NKV * HD];
__device__ float g_qT[(size_t)BATCH * NH * SEQ * HD];     // [b,h,s,d] tf32-rounded
__device__ float g_kT[(size_t)BATCH * NKV * SEQ * HD];    // tf32-rounded
__device__ float g_vT[(size_t)BATCH * NKV * SEQ * HD];    // tf32-rounded
__device__ float g_attn[(size_t)BATCH * SEQ * NH * HD];   // [b*s, 4096] tf32-rounded
__device__ float g_xr[(size_t)BATCH * SEQ * BDIM];        // tf32-rounded x
__device__ float g_wqr[(size_t)NH * HD * BDIM];           // tf32-rounded weights
__device__ float g_wkr[(size_t)NKV * HD * BDIM];
__device__ float g_wvr[(size_t)NKV * HD * BDIM];
__device__ float g_wor[(size_t)BDIM * NH * HD];

// ---------------- small helpers ------------------------------------------------
__device__ __forceinline__ uint32_t f2t(float x) {
    uint32_t u;
    asm("cvt.rna.tf32.f32 %0, %1;" : "=r"(u) : "f"(x));
    return u;
}

__device__ __forceinline__ void cp16(void* dst, const void* src) {
    uint32_t d = (uint32_t)__cvta_generic_to_shared(dst);
    asm volatile("cp.async.cg.shared.global [%0], [%1], 16;" :: "r"(d), "l"(src));
}
#define CP_COMMIT() asm volatile("cp.async.commit_group;")
#define CP_WAIT1()  asm volatile("cp.async.wait_group 1;")

typedef wmma::fragment<wmma::matrix_a, 16, 16, 8, wmma::precision::tf32, wmma::row_major> FragA;
typedef wmma::fragment<wmma::matrix_b, 16, 16, 8, wmma::precision::tf32, wmma::col_major> FragBc;
typedef wmma::fragment<wmma::accumulator, 16, 16, 8, float> FragC;

// ---------------- GEMM: C[M,N] = A[M,K] * W[N,K]^T  (tf32, pre-rounded) --------
// CTA 128x128, 8 warps (4x2), warp tile 32x64. GSTG=3, smem 110592B ->
// 2 CTAs/SM (4 warps/SMSP) for latency hiding. No CVT in the loop.
#define GBM 128
#define GBN 128
#define GBK 32
#define GLD 36                          // (4r+c) mod 32 distinct -> conflict-free
#define GAS (GBM * GLD)                 // 4608 floats
#define GSTAGE (2 * GAS)                // 9216 floats per stage
#define GSTG 3
#define GEMM_SMEM_BYTES (GSTG * GSTAGE * 4)   // 110592 B

__device__ __forceinline__ void gemm_load_stage(
    float* st, const float* A, const float* W, int bm, int bn, int K, int k0, int tid)
{
    float* As = st;
    float* Bs = st + GAS;
    #pragma unroll
    for (int v = 0; v < 4; v++) {
        int idx = tid + v * 256;        // 0..1023
        int r = idx >> 3;
        int seg = (idx & 7) * 4;
        cp16(As + r * GLD + seg, A + (size_t)(bm + r) * K + k0 + seg);
        cp16(Bs + r * GLD + seg, W + (size_t)(bn + r) * K + k0 + seg);
    }
}

__global__ __launch_bounds__(256, 2) void gemm_tf32_nt(
    const float* __restrict__ A, const float* __restrict__ W, float* __restrict__ C,
    int M, int N, int K)
{
    extern __shared__ float smg[];
    int bm = blockIdx.y * GBM;
    int bn = blockIdx.x * GBN;
    int tid = threadIdx.x;
    int warp = tid >> 5;
    int wr = warp >> 1;   // 0..3 : 32-row slab
    int wc = warp & 1;    // 0..1 : 64-col slab

    FragC acc[2][4];
    #pragma unroll
    for (int i = 0; i < 2; i++)
        #pragma unroll
        for (int j = 0; j < 4; j++)
            wmma::fill_fragment(acc[i][j], 0.0f);

    int nk = K / GBK;

    #pragma unroll
    for (int s = 0; s < GSTG - 1; s++) {
        if (s < nk) gemm_load_stage(smg + s * GSTAGE, A, W, bm, bn, K, s * GBK, tid);
        CP_COMMIT();
    }

    for (int ks = 0; ks < nk; ks++) {
        CP_WAIT1();
        __syncthreads();
        float* As = smg + (ks % GSTG) * GSTAGE;
        float* Bs = As + GAS;

        #pragma unroll
        for (int kk = 0; kk < GBK / 8; kk++) {
            FragA af[2];
            FragBc bf[4];
            #pragma unroll
            for (int i = 0; i < 2; i++)
                wmma::load_matrix_sync(af[i], As + (wr * 32 + i * 16) * GLD + kk * 8, GLD);
            #pragma unroll
            for (int j = 0; j < 4; j++)
                wmma::load_matrix_sync(bf[j], Bs + (wc * 64 + j * 16) * GLD + kk * 8, GLD);
            #pragma unroll
            for (int i = 0; i < 2; i++)
                #pragma unroll
                for (int j = 0; j < 4; j++)
                    wmma::mma_sync(acc[i][j], af[i], bf[j], acc[i][j]);
        }
        __syncthreads();

        int kn = ks + GSTG - 1;
        if (kn < nk) gemm_load_stage(smg + (kn % GSTG) * GSTAGE, A, W, bm, bn, K, kn * GBK, tid);
        CP_COMMIT();
    }

    #pragma unroll
    for (int i = 0; i < 2; i++)
        #pragma unroll
        for (int j = 0; j < 4; j++)
            wmma::store_matrix_sync(
                C + (size_t)(bm + wr * 32 + i * 16) * N + bn + wc * 64 + j * 16,
                acc[i][j], N, wmma::mem_row_major);
}

// ---------------- tf32 RNA pre-rounding ----------------------------------------
__global__ void round_tf32(const float* __restrict__ in, float* __restrict__ out, int n)
{
    int i = (blockIdx.x * blockDim.x + threadIdx.x) * 4;
    if (i >= n) return;
    float4 v = *(const float4*)(in + i);
    v.x = __uint_as_float(f2t(v.x));
    v.y = __uint_as_float(f2t(v.y));
    v.z = __uint_as_float(f2t(v.z));
    v.w = __uint_as_float(f2t(v.w));
    *(float4*)(out + i) = v;
}

// ---------------- RoPE + transpose [b,s,h,d] -> [b,h,s,d], tf32-rounded out ----
__global__ void rope_tr(const float* __restrict__ in, const float* __restrict__ fc,
                        const float* __restrict__ fs, float* __restrict__ outT,
                        int nh, int total)
{
    int idx = blockIdx.x * blockDim.x + threadIdx.x;
    if (idx >= total) return;
    int i = idx & 63;
    int t = idx >> 6;
    int h = t % nh; t /= nh;
    int s = t % SEQ;
    int b = t / SEQ;
    float c = fc[s * 64 + i];
    float sn = fs[s * 64 + i];
    size_t src = (((size_t)(b * SEQ + s)) * nh + h) * HD + 2 * i;
    float x0 = in[src];
    float x1 = in[src + 1];
    size_t dst = (((size_t)(b * nh + h)) * SEQ + s) * HD + 2 * i;
    outT[dst]     = __uint_as_float(f2t(x0 * c - x1 * sn));
    outT[dst + 1] = __uint_as_float(f2t(x0 * sn + x1 * c));
}

__global__ void tr_v(const float* __restrict__ in, float* __restrict__ outT, int total)
{
    int idx = blockIdx.x * blockDim.x + threadIdx.x;
    if (idx >= total) return;
    int d = idx & 127;
    int t = idx >> 7;
    int h = t % NKV; t /= NKV;
    int s = t % SEQ;
    int b = t / SEQ;
    outT[(((size_t)(b * NKV + h)) * SEQ + s) * HD + d] =
        __uint_as_float(f2t(in[(((size_t)(b * SEQ + s)) * NKV + h) * HD + d]));
}

// ---------------- Flash attention v2 (causal, GQA), raw tf32 mma ---------------
__device__ __forceinline__ void mma8(float* c, const uint32_t* a, uint32_t b0, uint32_t b1) {
    asm volatile(
        "mma.sync.aligned.m16n8k8.row.col.f32.tf32.tf32.f32 "
        "{%0,%1,%2,%3},{%4,%5,%6,%7},{%8,%9},{%0,%1,%2,%3};"
        : "+f"(c[0]), "+f"(c[1]), "+f"(c[2]), "+f"(c[3])
        : "r"(a[0]), "r"(a[1]), "r"(a[2]), "r"(a[3]), "r"(b0), "r"(b1));
}

#define KLD 132
#define VLD 136
#define KVSTG_FLOATS (64 * KLD + 64 * VLD)
#define ATTN_SMEM_BYTES (2 * KVSTG_FLOATS * 4)

__device__ __forceinline__ void attn_load_kv(
    float* stage, const float* Kt, const float* Vt, int tid)
{
    float* Ks = stage;
    float* Vs = stage + 64 * KLD;
    #pragma unroll
    for (int v = 0; v < 8; v++) {
        int c = tid + v * 256;
        int r = c >> 5;
        int c4 = (c & 31) * 4;
        cp16(Ks + r * KLD + c4, Kt + (size_t)r * HD + c4);
        cp16(Vs + r * VLD + c4, Vt + (size_t)r * HD + c4);
    }
}

__global__ __launch_bounds__(256) void attn_fa2(
    const float* __restrict__ qT, const float* __restrict__ kT,
    const float* __restrict__ vT, float* __restrict__ attn_out)
{
    extern __shared__ float sma[];
    int qt = blockIdx.x;
    int h  = blockIdx.y;
    int b  = blockIdx.z;
    int g  = h >> 2;
    int tid = threadIdx.x;
    int warp = tid >> 5;
    int lane = tid & 31;
    int r0 = lane >> 2;
    int q0 = lane & 3;

    const float* Qg = qT + (((size_t)(b * NH + h)) * SEQ + qt * 128 + warp * 16) * HD;
    const float* Kg = kT + ((size_t)(b * NKV + g)) * SEQ * HD;
    const float* Vg = vT + ((size_t)(b * NKV + g)) * SEQ * HD;
    const float qscale = 0.088388347648318447f;

    uint32_t qa[16][4];
    #pragma unroll
    for (int kk = 0; kk < 16; kk++) {
        qa[kk][0] = f2t(Qg[(size_t)r0 * HD + kk * 8 + q0] * qscale);
        qa[kk][1] = f2t(Qg[(size_t)(r0 + 8) * HD + kk * 8 + q0] * qscale);
        qa[kk][2] = f2t(Qg[(size_t)r0 * HD + kk * 8 + q0 + 4] * qscale);
        qa[kk][3] = f2t(Qg[(size_t)(r0 + 8) * HD + kk * 8 + q0 + 4] * qscale);
    }

    float of[16][4];
    #pragma unroll
    for (int dn = 0; dn < 16; dn++) {
        of[dn][0] = 0.0f; of[dn][1] = 0.0f; of[dn][2] = 0.0f; of[dn][3] = 0.0f;
    }
    float m_lo = -1e30f, m_hi = -1e30f, l_lo = 0.0f, l_hi = 0.0f;
    int row_lo = qt * 128 + warp * 16 + r0;
    int row_hi = row_lo + 8;
    int ktmax = 2 * qt + 1;

    attn_load_kv(sma, Kg, Vg, tid);
    CP_COMMIT();

    for (int kt = 0; kt <= ktmax; kt++) {
        if (kt < ktmax)
            attn_load_kv(sma + ((kt + 1) & 1) * KVSTG_FLOATS,
                         Kg + (size_t)(kt + 1) * 64 * HD,
                         Vg + (size_t)(kt + 1) * 64 * HD, tid);
        CP_COMMIT();
        CP_WAIT1();
        __syncthreads();

        bool active = (kt * 64) <= (qt * 128 + warp * 16 + 15);
        if (active) {
            const float* Ks = sma + (kt & 1) * KVSTG_FLOATS;
            const float* Vs = Ks + 64 * KLD;

            float sf[8][4];
            #pragma unroll
            for (int nn = 0; nn < 8; nn++) {
                sf[nn][0] = 0.0f; sf[nn][1] = 0.0f; sf[nn][2] = 0.0f; sf[nn][3] = 0.0f;
            }
            #pragma unroll
            for (int nn = 0; nn < 8; nn++) {
                const uint32_t* Kb = (const uint32_t*)(Ks + (nn * 8 + r0) * KLD);
                #pragma unroll
                for (int kk = 0; kk < 16; kk++) {
                    uint32_t b0 = Kb[kk * 8 + q0];
                    uint32_t b1 = Kb[kk * 8 + q0 + 4];
                    mma8(sf[nn], qa[kk], b0, b1);
                }
            }

            if (kt >= 2 * qt) {
                #pragma unroll
                for (int nn = 0; nn < 8; nn++) {
                    int c0 = kt * 64 + nn * 8 + 2 * q0;
                    if (c0     > row_lo) sf[nn][0] = -1e30f;
                    if (c0 + 1 > row_lo) sf[nn][1] = -1e30f;
                    if (c0     > row_hi) sf[nn][2] = -1e30f;
                    if (c0 + 1 > row_hi) sf[nn][3] = -1e30f;
                }
            }

            float mx_lo = -1e30f, mx_hi = -1e30f;
            #pragma unroll
            for (int nn = 0; nn < 8; nn++) {
                mx_lo = fmaxf(mx_lo, fmaxf(sf[nn][0], sf[nn][1]));
                mx_hi = fmaxf(mx_hi, fmaxf(sf[nn][2], sf[nn][3]));
            }
            mx_lo = fmaxf(mx_lo, __shfl_xor_sync(0xffffffffu, mx_lo, 1));
            mx_lo = fmaxf(mx_lo, __shfl_xor_sync(0xffffffffu, mx_lo, 2));
            mx_hi = fmaxf(mx_hi, __shfl_xor_sync(0xffffffffu, mx_hi, 1));
            mx_hi = fmaxf(mx_hi, __shfl_xor_sync(0xffffffffu, mx_hi, 2));

            float nm_lo = fmaxf(m_lo, mx_lo);
            float nm_hi = fmaxf(m_hi, mx_hi);
            float al_lo = __expf(m_lo - nm_lo);
            float al_hi = __expf(m_hi - nm_hi);
            m_lo = nm_lo; m_hi = nm_hi;

            float s_lo = 0.0f, s_hi = 0.0f;
            #pragma unroll
            for (int nn = 0; nn < 8; nn++) {
                sf[nn][0] = __expf(sf[nn][0] - m_lo); s_lo += sf[nn][0];
                sf[nn][1] = __expf(sf[nn][1] - m_lo); s_lo += sf[nn][1];
                sf[nn][2] = __expf(sf[nn][2] - m_hi); s_hi += sf[nn][2];
                sf[nn][3] = __expf(sf[nn][3] - m_hi); s_hi += sf[nn][3];
            }
            s_lo += __shfl_xor_sync(0xffffffffu, s_lo, 1);
            s_lo += __shfl_xor_sync(0xffffffffu, s_lo, 2);
            s_hi += __shfl_xor_sync(0xffffffffu, s_hi, 1);
            s_hi += __shfl_xor_sync(0xffffffffu, s_hi, 2);
            l_lo = l_lo * al_lo + s_lo;
            l_hi = l_hi * al_hi + s_hi;

            #pragma unroll
            for (int dn = 0; dn < 16; dn++) {
                of[dn][0] *= al_lo; of[dn][1] *= al_lo;
                of[dn][2] *= al_hi; of[dn][3] *= al_hi;
            }

            int base = lane & ~3;
            int srcA = base | (q0 >> 1);
            int srcB = base | ((q0 >> 1) + 2);
            #pragma unroll
            for (int kk = 0; kk < 8; kk++) {
                float v0 = __shfl_sync(0xffffffffu, sf[kk][0], srcA);
                float v1 = __shfl_sync(0xffffffffu, sf[kk][1], srcA);
                float v2 = __shfl_sync(0xffffffffu, sf[kk][2], srcA);
                float v3 = __shfl_sync(0xffffffffu, sf[kk][3], srcA);
                float w0 = __shfl_sync(0xffffffffu, sf[kk][0], srcB);
                float w1 = __shfl_sync(0xffffffffu, sf[kk][1], srcB);
                float w2 = __shfl_sync(0xffffffffu, sf[kk][2], srcB);
                float w3 = __shfl_sync(0xffffffffu, sf[kk][3], srcB);
                uint32_t pa[4];
                pa[0] = f2t((q0 & 1) ? v1 : v0);
                pa[1] = f2t((q0 & 1) ? v3 : v2);
                pa[2] = f2t((q0 & 1) ? w1 : w0);
                pa[3] = f2t((q0 & 1) ? w3 : w2);
                const uint32_t* Vb0 = (const uint32_t*)(Vs + (kk * 8 + q0) * VLD) + r0;
                const uint32_t* Vb1 = (const uint32_t*)(Vs + (kk * 8 + q0 + 4) * VLD) + r0;
                #pragma unroll
                for (int dn = 0; dn < 16; dn++) {
                    uint32_t b0 = Vb0[dn * 8];
                    uint32_t b1 = Vb1[dn * 8];
                    mma8(of[dn], pa, b0, b1);
                }
            }
        }
        __syncthreads();
    }

    // normalize + tf32-round + write (feeds final GEMM directly)
    float inv_lo = 1.0f / l_lo;
    float inv_hi = 1.0f / l_hi;
    float* Olo = attn_out + (size_t)(b * SEQ + row_lo) * (NH * HD) + h * HD;
    float* Ohi = attn_out + (size_t)(b * SEQ + row_hi) * (NH * HD) + h * HD;
    #pragma unroll
    for (int dn = 0; dn < 16; dn++) {
        int c = dn * 8 + 2 * q0;
        *(float2*)(Olo + c) = make_float2(
            __uint_as_float(f2t(of[dn][0] * inv_lo)),
            __uint_as_float(f2t(of[dn][1] * inv_lo)));
        *(float2*)(Ohi + c) = make_float2(
            __uint_as_float(f2t(of[dn][2] * inv_hi)),
            __uint_as_float(f2t(of[dn][3] * inv_hi)));
    }
}

// ---------------- launch ------------------------------------------------------
extern "C" void kernel_launch(void* const* d_in, const int* in_sizes, int n_in,
                              void* d_out, int out_size)
{
    const float* x  = (const float*)d_in[0];
    const float* wq = (const float*)d_in[1];
    const float* wk = (const float*)d_in[2];
    const float* wv = (const float*)d_in[3];
    const float* wo = (const float*)d_in[4];
    const float* fc = (const float*)d_in[5];
    const float* fs = (const float*)d_in[6];
    float* out = (float*)d_out;

    float *qbuf, *kbuf, *vbuf, *qT, *kT, *vT, *attn, *xr, *wqr, *wkr, *wvr, *wor;
    cudaGetSymbolAddress((void**)&qbuf, g_qbuf);
    cudaGetSymbolAddress((void**)&kbuf, g_kbuf);
    cudaGetSymbolAddress((void**)&vbuf, g_vbuf);
    cudaGetSymbolAddress((void**)&qT, g_qT);
    cudaGetSymbolAddress((void**)&kT, g_kT);
    cudaGetSymbolAddress((void**)&vT, g_vT);
    cudaGetSymbolAddress((void**)&attn, g_attn);
    cudaGetSymbolAddress((void**)&xr, g_xr);
    cudaGetSymbolAddress((void**)&wqr, g_wqr);
    cudaGetSymbolAddress((void**)&wkr, g_wkr);
    cudaGetSymbolAddress((void**)&wvr, g_wvr);
    cudaGetSymbolAddress((void**)&wor, g_wor);

    const int M = BATCH * SEQ;  // 4096

    cudaFuncSetAttribute(gemm_tf32_nt, cudaFuncAttributeMaxDynamicSharedMemorySize,
                         GEMM_SMEM_BYTES);
    cudaFuncSetAttribute(attn_fa2, cudaFuncAttributeMaxDynamicSharedMemorySize,
                         ATTN_SMEM_BYTES);

    const int RB = 256;
    int nx = M * BDIM;
    int nwq = NH * HD * BDIM;
    int nwk = NKV * HD * BDIM;

    // launches 0-4: all rounding up front (puts Q-GEMM at ncu's -s 5 slot)
    round_tf32<<<nx / 4 / RB, RB>>>(x, xr, nx);
    round_tf32<<<nwq / 4 / RB, RB>>>(wq, wqr, nwq);
    round_tf32<<<nwk / 4 / RB, RB>>>(wk, wkr, nwk);
    round_tf32<<<nwk / 4 / RB, RB>>>(wv, wvr, nwk);
    round_tf32<<<nwq / 4 / RB, RB>>>(wo, wor, nwq);

    // launch 5: the 4096^3 Q projection (ncu target)
    gemm_tf32_nt<<<dim3((NH * HD) / GBN, M / GBM), 256, GEMM_SMEM_BYTES>>>(
        xr, wqr, qbuf, M, NH * HD, BDIM);
    gemm_tf32_nt<<<dim3((NKV * HD) / GBN, M / GBM), 256, GEMM_SMEM_BYTES>>>(
        xr, wkr, kbuf, M, NKV * HD, BDIM);
    gemm_tf32_nt<<<dim3((NKV * HD) / GBN, M / GBM), 256, GEMM_SMEM_BYTES>>>(
        xr, wvr, vbuf, M, NKV * HD, BDIM);

    int nq = M * NH * (HD / 2);
    rope_tr<<<(nq + 255) / 256, 256>>>(qbuf, fc, fs, qT, NH, nq);
    int nk = M * NKV * (HD / 2);
    rope_tr<<<(nk + 255) / 256, 256>>>(kbuf, fc, fs, kT, NKV, nk);
    int nv = M * NKV * HD;
    tr_v<<<(nv + 255) / 256, 256>>>(vbuf, vT, nv);

    attn_fa2<<<dim3(SEQ / 128, NH, BATCH), 256, ATTN_SMEM_BYTES>>>(qT, kT, vT, attn);

    gemm_tf32_nt<<<dim3(BDIM / GBN, M / GBM), 256, GEMM_SMEM_BYTES>>>(
        attn, wor, out, M, BDIM, NH * HD);
}